// round 5
// baseline (speedup 1.0000x reference)
#include <cuda_runtime.h>
#include <math.h>

// ---------------- problem constants ----------------
#define HID 128
#define INP 320
#define CIN 448           // HID + INP
#define BATCH 8
#define IMH 64
#define IMW 128

// tile: 4 rows x 32 cols = 128 pixels per block
#define TH 4
#define TW 32
#define TP (TH*TW)        // 128
#define KC 16             // channels per k-chunk
#define NCHUNK (CIN/KC)   // 28

// ---------------- dynamic smem layout (floats) ----------------
// s_in  : 2 x KC x 205   (halo tile, stride 205; rows 6x34 used)
// s_wp  : 2 x KC x 128   (pw weight chunk, [k][o])
// s_dw  : KC x 128       (dw results [k][p])
// s_wd  : CIN x 9        (all dw weights, preloaded once)
#define OFF_IN0   0
#define OFF_IN1   (KC*205)
#define OFF_WP0   (2*KC*205)
#define OFF_WP1   (2*KC*205 + KC*128)
#define OFF_DW    (2*KC*205 + 2*KC*128)
#define OFF_WD    (2*KC*205 + 2*KC*128 + KC*128)
#define SMEM_FLOATS (2*KC*205 + 3*KC*128 + CIN*9)
#define SMEM_BYTES (SMEM_FLOATS*4)   // 66944

// ---------------- device scratch ----------------
__device__ float g_z [BATCH*HID*IMH*IMW];   // sigmoid(z-gate)
__device__ float g_rh[BATCH*HID*IMH*IMW];   // r*h
__device__ float g_wd [3][CIN*9];           // quantized dw weights [c][3][3]
__device__ float g_wpT[3][CIN*HID];         // quantized pw weights transposed [c][o]

// ---------------- helpers ----------------
__device__ __forceinline__ unsigned long long pack2(float a, float b) {
    unsigned long long r;
    asm("mov.b64 %0, {%1, %2};" : "=l"(r)
        : "r"(__float_as_uint(a)), "r"(__float_as_uint(b)));
    return r;
}
__device__ __forceinline__ void fma2(unsigned long long& d,
                                     unsigned long long a,
                                     unsigned long long b) {
    asm("fma.rn.f32x2 %0, %1, %2, %0;" : "+l"(d) : "l"(a), "l"(b));
}
__device__ __forceinline__ float sigmoidf_(float v) {
    return 1.0f / (1.0f + expf(-v));
}
__device__ __forceinline__ void cpa4(unsigned int dst, const float* src, bool ok) {
    asm volatile("cp.async.ca.shared.global [%0], [%1], 4, %2;"
                 :: "r"(dst), "l"(src), "r"(ok ? 4 : 0) : "memory");
}
__device__ __forceinline__ void cpa16(unsigned int dst, const float* src) {
    asm volatile("cp.async.cg.shared.global [%0], [%1], 16;"
                 :: "r"(dst), "l"(src) : "memory");
}
__device__ __forceinline__ void cp_commit() {
    asm volatile("cp.async.commit_group;" ::: "memory");
}
__device__ __forceinline__ void cp_wait1() {
    asm volatile("cp.async.wait_group 1;" ::: "memory");
}

// ---------------- weight fake-quant prep ----------------
__global__ void quant_prep_kernel(const float* wdz, const float* wpz,
                                  const float* wdr, const float* wpr,
                                  const float* wdq, const float* wpq) {
    const int which = blockIdx.x;
    const float* src = nullptr; int n = 0; float* dst_dw = nullptr; float* dst_pw = nullptr;
    switch (which) {
        case 0: src = wdz; n = CIN*9;   dst_dw = g_wd[0];  break;
        case 1: src = wpz; n = CIN*HID; dst_pw = g_wpT[0]; break;
        case 2: src = wdr; n = CIN*9;   dst_dw = g_wd[1];  break;
        case 3: src = wpr; n = CIN*HID; dst_pw = g_wpT[1]; break;
        case 4: src = wdq; n = CIN*9;   dst_dw = g_wd[2];  break;
        default:src = wpq; n = CIN*HID; dst_pw = g_wpT[2]; break;
    }
    __shared__ float red[256];
    __shared__ float s_scale;
    const int tid = threadIdx.x;
    float m = 0.0f;
    for (int i = tid; i < n; i += 256) m = fmaxf(m, fabsf(src[i]));
    red[tid] = m;
    __syncthreads();
    for (int s = 128; s > 0; s >>= 1) {
        if (tid < s) red[tid] = fmaxf(red[tid], red[tid + s]);
        __syncthreads();
    }
    if (tid == 0) s_scale = fmaxf(red[0], 1e-8f) / 127.0f;
    __syncthreads();
    const float scale = s_scale;
    for (int i = tid; i < n; i += 256) {
        float q = rintf(src[i] / scale);            // round-half-even == jnp.round
        q = fminf(fmaxf(q, -128.0f), 127.0f);
        const float v = q * scale;
        if (dst_dw) {
            dst_dw[i] = v;
        } else {
            const int o = i / CIN;                  // wp is [O][C]
            const int c = i - o * CIN;
            dst_pw[c * HID + o] = v;                // store transposed [c][o]
        }
    }
}

// ---------------- fused gate kernel ----------------
// MODE 0: z = sigmoid(pw(dw(hx)))             -> g_z
// MODE 1: rh = sigmoid(pw(dw(hx))) * h        -> g_rh
// MODE 2: out = (1-z)*h + z*tanh(pw(dw(rhx))) -> dout
template <int MODE>
__global__ void __launch_bounds__(256, 2)
gate_kernel(const float* __restrict__ h, const float* __restrict__ x,
            const float* __restrict__ bd, const float* __restrict__ bp,
            float* __restrict__ dout) {
    extern __shared__ float smem[];
    float* s_dw = smem + OFF_DW;
    float* s_wd = smem + OFF_WD;
    const unsigned int smem_u32 = (unsigned int)__cvta_generic_to_shared(smem);

    const int tid = threadIdx.x;
    const int b  = blockIdx.z;
    const int y0 = blockIdx.y << 2;    // TH=4
    const int x0 = blockIdx.x << 5;    // TW=32

    const float* in0 = (MODE == 2) ? g_rh : h;   // first 128 channels
    const float* wpg = g_wpT[MODE];
    const float* wdg = g_wd[MODE];

    // staging thread mapping: one channel per 16-lane group
    const int kk  = tid >> 4;
    const int l16 = tid & 15;

    // GEMM thread mapping: out-pairs o = 2*og + 32*i (+d), pixels p = 8*pg + j
    const int og = tid & 15;
    const int pg = tid >> 4;

    // dw thread mapping
    const int dk  = tid >> 4;
    const int dg  = tid & 15;
    const int drr = dg >> 2;
    const int dcg = (dg & 3) << 3;

    unsigned long long acc[4][8];
#pragma unroll
    for (int i = 0; i < 4; i++)
#pragma unroll
        for (int j = 0; j < 8; j++) acc[i][j] = 0ULL;

    // ---- staging lambdas (manual) ----
    // input halo tile for chunk ci into buffer buf: KC x 6 x 34, zero-padded OOB
    auto stage_in = [&](int ci, int buf) {
        const int cg = ci * KC + kk;
        const float* pl = (cg < HID)
            ? (in0 + (((size_t)b * HID + cg) << 13))
            : (x   + (((size_t)b * INP + (cg - HID)) << 13));
        const unsigned int sb = smem_u32 + ((buf ? OFF_IN1 : OFF_IN0) + kk * 205) * 4;
#pragma unroll
        for (int row = 0; row < 6; row++) {
            const int gy = y0 + row - 1;
            const bool rok = (unsigned)gy < (unsigned)IMH;
#pragma unroll
            for (int s = 0; s < 3; s++) {
                const int xx = l16 + (s << 4);
                if (xx < 34) {
                    const int gx = x0 + xx - 1;
                    const bool ok = rok && ((unsigned)gx < (unsigned)IMW);
                    const int goff = ok ? ((gy << 7) + gx) : 0;
                    cpa4(sb + (row * 34 + xx) * 4, pl + goff, ok);
                }
            }
        }
    };
    auto stage_wp = [&](int ci, int buf) {
        const float* src = wpg + (ci << 11);  // KC*128 = 2048 floats per chunk
        const unsigned int db = smem_u32 + (buf ? OFF_WP1 : OFF_WP0) * 4;
        cpa16(db + tid * 16,          src + (tid << 2));
        cpa16(db + (tid + 256) * 16,  src + ((tid + 256) << 2));
    };

    // ---- prologue: all dw weights + chunk 0 ----
    {
        // CIN*9 = 4032 floats = 1008 float4
        const unsigned int db = smem_u32 + OFF_WD * 4;
#pragma unroll
        for (int t = 0; t < 4; t++) {
            const int i = tid + (t << 8);
            if (i < 1008) cpa16(db + i * 16, wdg + (i << 2));
        }
        stage_in(0, 0);
        stage_wp(0, 0);
        cp_commit();
    }

    for (int ci = 0; ci < NCHUNK; ci++) {
        const int buf = ci & 1;
        __syncthreads();                       // all warps done with gemm(ci-1)
        if (ci + 1 < NCHUNK) {
            stage_in(ci + 1, buf ^ 1);
            stage_wp(ci + 1, buf ^ 1);
        }
        cp_commit();                            // (possibly empty) group
        cp_wait1();                             // chunk ci's group complete
        __syncthreads();                        // visible to all threads

        const float* s_in_b = smem + (buf ? OFF_IN1 : OFF_IN0);
        const float* s_wp_b = smem + (buf ? OFF_WP1 : OFF_WP0);

        // --- depthwise 3x3 (+ bias) -> s_dw[k][p] ---
        {
            const int c0 = ci * KC;
            float w9[9];
#pragma unroll
            for (int j = 0; j < 9; j++) w9[j] = s_wd[(c0 + dk) * 9 + j];
            const float bdv = __ldg(&bd[c0 + dk]);
            const float* ib = &s_in_b[dk * 205 + drr * 34 + dcg];
            float rin[3][10];
#pragma unroll
            for (int dy = 0; dy < 3; dy++)
#pragma unroll
                for (int xx = 0; xx < 10; xx++) rin[dy][xx] = ib[dy * 34 + xx];
            float o8[8];
#pragma unroll
            for (int c = 0; c < 8; c++) {
                float a = bdv;
#pragma unroll
                for (int dy = 0; dy < 3; dy++)
#pragma unroll
                    for (int dx = 0; dx < 3; dx++)
                        a = fmaf(w9[dy * 3 + dx], rin[dy][c + dx], a);
                o8[c] = a;
            }
            float4* dp = reinterpret_cast<float4*>(&s_dw[(dk << 7) + (drr << 5) + dcg]);
            dp[0] = make_float4(o8[0], o8[1], o8[2], o8[3]);
            dp[1] = make_float4(o8[4], o8[5], o8[6], o8[7]);
        }
        __syncthreads();

        // --- pointwise GEMM accumulate: packed f32x2 (out-pairs) ---
#pragma unroll
        for (int k = 0; k < KC; k++) {
            const float* wk = &s_wp_b[(k << 7) + (og << 1)];
            const unsigned long long w0 = *reinterpret_cast<const unsigned long long*>(wk);
            const unsigned long long w1 = *reinterpret_cast<const unsigned long long*>(wk + 32);
            const unsigned long long w2 = *reinterpret_cast<const unsigned long long*>(wk + 64);
            const unsigned long long w3 = *reinterpret_cast<const unsigned long long*>(wk + 96);
            const float* dkp = &s_dw[(k << 7) + (pg << 3)];
            const float4 d0 = *reinterpret_cast<const float4*>(dkp);
            const float4 d1 = *reinterpret_cast<const float4*>(dkp + 4);
            const float dv8[8] = {d0.x, d0.y, d0.z, d0.w, d1.x, d1.y, d1.z, d1.w};
#pragma unroll
            for (int j = 0; j < 8; j++) {
                const unsigned long long dd = pack2(dv8[j], dv8[j]);
                fma2(acc[0][j], w0, dd);
                fma2(acc[1][j], w1, dd);
                fma2(acc[2][j], w2, dd);
                fma2(acc[3][j], w3, dd);
            }
        }
    }

    // ---------------- epilogue: stage through smem for coalesced stores ----------------
    float* s_ep = smem;   // reuse s_in region (needs 16*129 = 2064 floats)
#pragma unroll
    for (int i = 0; i < 4; i++) {
#pragma unroll
        for (int d = 0; d < 2; d++) {
            __syncthreads();
#pragma unroll
            for (int j = 0; j < 8; j++) {
                const unsigned long long a = acc[i][j];
                const unsigned int bits = d ? (unsigned int)(a >> 32) : (unsigned int)a;
                s_ep[og * 129 + (pg << 3) + j] = __uint_as_float(bits);
            }
            __syncthreads();
#pragma unroll
            for (int it = 0; it < 8; it++) {
                const int e   = tid + (it << 8);
                const int ogs = e >> 7;
                const int p   = e & 127;
                const int c   = (i << 5) + (ogs << 1) + d;
                const float v = s_ep[ogs * 129 + p] + __ldg(&bp[c]);
                const int pr = p >> 5, pc = p & 31;
                const int gidx = (((b << 7) + c) << 13) + ((y0 + pr) << 7) + (x0 + pc);
                if (MODE == 0) {
                    g_z[gidx] = sigmoidf_(v);
                } else if (MODE == 1) {
                    g_rh[gidx] = h[gidx] * sigmoidf_(v);
                } else {
                    const float zz = g_z[gidx];
                    const float hv = h[gidx];
                    dout[gidx] = fmaf(zz, tanhf(v) - hv, hv);   // (1-z)h + z*q
                }
            }
        }
    }
}

// ---------------- launch ----------------
extern "C" void kernel_launch(void* const* d_in, const int* in_sizes, int n_in,
                              void* d_out, int out_size) {
    const float* h   = (const float*)d_in[0];
    const float* x   = (const float*)d_in[1];
    const float* wdz = (const float*)d_in[2];
    const float* bdz = (const float*)d_in[3];
    const float* wpz = (const float*)d_in[4];
    const float* bpz = (const float*)d_in[5];
    const float* wdr = (const float*)d_in[6];
    const float* bdr = (const float*)d_in[7];
    const float* wpr = (const float*)d_in[8];
    const float* bpr = (const float*)d_in[9];
    const float* wdq = (const float*)d_in[10];
    const float* bdq = (const float*)d_in[11];
    const float* wpq = (const float*)d_in[12];
    const float* bpq = (const float*)d_in[13];
    float* out = (float*)d_out;

    cudaFuncSetAttribute(gate_kernel<0>, cudaFuncAttributeMaxDynamicSharedMemorySize, SMEM_BYTES);
    cudaFuncSetAttribute(gate_kernel<1>, cudaFuncAttributeMaxDynamicSharedMemorySize, SMEM_BYTES);
    cudaFuncSetAttribute(gate_kernel<2>, cudaFuncAttributeMaxDynamicSharedMemorySize, SMEM_BYTES);

    quant_prep_kernel<<<6, 256>>>(wdz, wpz, wdr, wpr, wdq, wpq);

    dim3 grid(IMW / TW, IMH / TH, BATCH);   // (4, 16, 8) = 512 blocks
    gate_kernel<0><<<grid, 256, SMEM_BYTES>>>(h, x, bdz, bpz, nullptr);
    gate_kernel<1><<<grid, 256, SMEM_BYTES>>>(h, x, bdr, bpr, nullptr);
    gate_kernel<2><<<grid, 256, SMEM_BYTES>>>(h, x, bdq, bpq, out);
}

// round 8
// speedup vs baseline: 2.0326x; 2.0326x over previous
#include <cuda_runtime.h>
#include <cuda_bf16.h>
#include <stdint.h>
#include <math.h>

#define HID 128
#define INP 320
#define CIN 448
#define BATCH 8
#define IMH 64
#define IMW 128
#define NCH 14                    // 448/32 channel chunks

typedef unsigned long long u64;

// ---- smem byte layout ----
#define OFF_A   1024              // 2 x 16384 (A weight tiles, SW128, [o][64 bf16])
#define OFF_B   (OFF_A + 32768)   // 2 x 16384 (B act tiles, SW128, [px][64 bf16])
#define OFF_WD  (OFF_B + 32768)   // 448*9*4 = 16128 (dw weights fp32)
#define OFF_IN  (OFF_WD + 16128)  // 2 x 32 x 209 floats (halo tiles)
#define IN_STRIDE 209
#define SMEM_BYTES (OFF_IN + 2*32*IN_STRIDE*4)   // 136192
#define EP_STRIDE 132             // epilogue stage stride (floats)

// ---- device scratch ----
__device__ float g_z [BATCH*HID*IMH*IMW];
__device__ float g_rh[BATCH*HID*IMH*IMW];
__device__ float g_wd[3][CIN*9];
__device__ __align__(16) __nv_bfloat16 g_wpA[3][NCH*8192]; // pre-swizzled A tiles
__device__ float g_wpscale[3];

// ---- helpers ----
__device__ __forceinline__ unsigned swz(unsigned off) { return off ^ ((off >> 3) & 0x70); }
__device__ __forceinline__ float sigmoidf_(float v) { return 1.0f / (1.0f + expf(-v)); }
__device__ __forceinline__ void cpa4(unsigned d, const float* s, bool ok) {
    asm volatile("cp.async.ca.shared.global [%0], [%1], 4, %2;"
                 :: "r"(d), "l"(s), "r"(ok ? 4 : 0) : "memory");
}
__device__ __forceinline__ void cpa16(unsigned d, const void* s) {
    asm volatile("cp.async.cg.shared.global [%0], [%1], 16;" :: "r"(d), "l"(s) : "memory");
}
__device__ __forceinline__ void cp_commit() { asm volatile("cp.async.commit_group;" ::: "memory"); }
__device__ __forceinline__ void cp_wait1()  { asm volatile("cp.async.wait_group 1;" ::: "memory"); }
__device__ __forceinline__ unsigned pack_bf2(float up, float lo) {  // {upper=up, lower=lo}
    unsigned r;
    asm("cvt.rn.bf16x2.f32 %0, %1, %2;" : "=r"(r) : "f"(up), "f"(lo));
    return r;
}
__device__ __forceinline__ void ldm_x4(unsigned addr, unsigned* r) {
    asm volatile("ldmatrix.sync.aligned.m8n8.x4.shared.b16 {%0,%1,%2,%3}, [%4];"
                 : "=r"(r[0]), "=r"(r[1]), "=r"(r[2]), "=r"(r[3]) : "r"(addr));
}
__device__ __forceinline__ void mma16816(float* d, const unsigned* a, unsigned b0, unsigned b1) {
    asm volatile("mma.sync.aligned.m16n8k16.row.col.f32.bf16.bf16.f32 "
                 "{%0,%1,%2,%3}, {%4,%5,%6,%7}, {%8,%9}, {%0,%1,%2,%3};"
                 : "+f"(d[0]), "+f"(d[1]), "+f"(d[2]), "+f"(d[3])
                 : "r"(a[0]), "r"(a[1]), "r"(a[2]), "r"(a[3]), "r"(b0), "r"(b1));
}

// ---- weight fake-quant prep ----
__global__ void quant_prep_kernel(const float* wdz, const float* wpz,
                                  const float* wdr, const float* wpr,
                                  const float* wdq, const float* wpq) {
    const int which = blockIdx.x;
    const float* src = nullptr; int n = 0; float* dst_dw = nullptr;
    __nv_bfloat16* dst_pw = nullptr; const int g = which >> 1;
    switch (which) {
        case 0: src = wdz; n = CIN*9;   dst_dw = g_wd[0];  break;
        case 1: src = wpz; n = CIN*HID; dst_pw = g_wpA[0]; break;
        case 2: src = wdr; n = CIN*9;   dst_dw = g_wd[1];  break;
        case 3: src = wpr; n = CIN*HID; dst_pw = g_wpA[1]; break;
        case 4: src = wdq; n = CIN*9;   dst_dw = g_wd[2];  break;
        default:src = wpq; n = CIN*HID; dst_pw = g_wpA[2]; break;
    }
    __shared__ float red[256];
    __shared__ float s_scale;
    const int tid = threadIdx.x;
    float m = 0.0f;
    for (int i = tid; i < n; i += 256) m = fmaxf(m, fabsf(src[i]));
    red[tid] = m; __syncthreads();
    for (int s = 128; s > 0; s >>= 1) {
        if (tid < s) red[tid] = fmaxf(red[tid], red[tid + s]);
        __syncthreads();
    }
    if (tid == 0) { s_scale = fmaxf(red[0], 1e-8f) / 127.0f; if (dst_pw) g_wpscale[g] = s_scale; }
    __syncthreads();
    const float scale = s_scale;
    for (int i = tid; i < n; i += 256) {
        float q = rintf(src[i] / scale);               // round-half-even == jnp.round
        q = fminf(fmaxf(q, -128.0f), 127.0f);
        if (dst_dw) {
            dst_dw[i] = q * scale;
        } else {
            // A tile: chunk ci, row o, col k (hi) & 32+k (lo) both = q (exact in bf16)
            const int o = i / CIN, c = i - o * CIN;
            const int ci = c >> 5, k = c & 31;
            const __nv_bfloat16 qb = __float2bfloat16(q);
            const unsigned o1 = (unsigned)((o << 7) + (k << 1));
            dst_pw[(ci << 13) + (swz(o1) >> 1)]      = qb;
            dst_pw[(ci << 13) + (swz(o1 + 64) >> 1)] = qb;
        }
    }
}

// ---- fused gate kernel ----
// MODE 0: z = sigmoid(pw(dw(hx)))             -> g_z
// MODE 1: rh = sigmoid(pw(dw(hx))) * h        -> g_rh
// MODE 2: out = (1-z)*h + z*tanh(pw(dw(rhx))) -> dout
template <int MODE>
__global__ void __launch_bounds__(256, 1)
gate_kernel(const float* __restrict__ h, const float* __restrict__ x,
            const float* __restrict__ bd, const float* __restrict__ bp,
            float* __restrict__ dout) {
    extern __shared__ __align__(1024) char smem[];
    float* smf = reinterpret_cast<float*>(smem);
    const unsigned su = (unsigned)__cvta_generic_to_shared(smem);

    const int tid = threadIdx.x;
    const int wid = tid >> 5;
    const int lid = tid & 31;
    const int b  = blockIdx.z;
    const int y0 = blockIdx.y << 2;
    const int x0 = blockIdx.x << 5;

    const float* in0 = (MODE == 2) ? g_rh : h;
    const float* s_wd = smf + OFF_WD / 4;

    // staging maps
    const int sch = tid >> 3, l8 = tid & 7;
    auto stage_in = [&](int ci, int buf) {
        const int cg = (ci << 5) + sch;
        const float* pl = (cg < HID) ? (in0 + (((size_t)b * HID + cg) << 13))
                                     : (x   + (((size_t)b * INP + (cg - HID)) << 13));
        const unsigned sb = su + OFF_IN + ((buf * 32 + sch) * IN_STRIDE) * 4;
#pragma unroll
        for (int row = 0; row < 6; row++) {
            const int gy = y0 + row - 1;
            const bool rok = (unsigned)gy < (unsigned)IMH;
#pragma unroll
            for (int s = 0; s < 5; s++) {
                const int col = l8 + (s << 3);
                if (col < 34) {
                    const int gx = x0 + col - 1;
                    const bool ok = rok && ((unsigned)gx < (unsigned)IMW);
                    cpa4(sb + (row * 34 + col) * 4, pl + (ok ? ((gy << 7) + gx) : 0), ok);
                }
            }
        }
    };
    auto stage_A = [&](int ci, int buf) {
        const char* src = reinterpret_cast<const char*>(g_wpA[MODE]) + (ci << 14);
        const unsigned dst = su + OFF_A + (buf << 14);
#pragma unroll
        for (int t = 0; t < 4; t++)
            cpa16(dst + tid * 16 + t * 4096, src + tid * 16 + t * 4096);
    };

    // prologue: dw weights + chunk 0
    {
        const char* srcw = reinterpret_cast<const char*>(g_wd[MODE]);
#pragma unroll
        for (int t = 0; t < 4; t++) {
            const int i = tid + (t << 8);
            if (i < 1008) cpa16(su + OFF_WD + i * 16, srcw + i * 16);
        }
        stage_in(0, 0);
        stage_A(0, 0);
        cp_commit();
    }

    // dw thread map: ch pair cp, pixel group pg (8 px)
    const int cp = tid & 15, pg = tid >> 4;
    const int pr = pg >> 2, pc0 = (pg & 3) << 3;

    // mma warp tiling: warp = (mw, nw); M-block 32, N-block 64
    const int mw = wid & 3, nw = wid >> 2;
    const int aRow = lid & 15, aChunk = (lid >> 4) << 4;           // bytes
    const int bRow = ((lid >> 4) << 3) + (lid & 7);
    const int bChunk = ((lid >> 3) & 1) << 4;                      // bytes

    float acc[2][8][4];
#pragma unroll
    for (int i = 0; i < 2; i++)
#pragma unroll
        for (int j = 0; j < 8; j++)
#pragma unroll
            for (int k = 0; k < 4; k++) acc[i][j][k] = 0.0f;

    for (int ci = 0; ci < NCH; ci++) {
        const int buf = ci & 1;
        __syncthreads();                     // all warps done reading buf^1 (mma ci-1, dw ci-1)
        if (ci + 1 < NCH) { stage_in(ci + 1, buf ^ 1); stage_A(ci + 1, buf ^ 1); }
        cp_commit();
        cp_wait1();                          // chunk ci staging complete
        __syncthreads();

        // depthwise 3x3 + bias for 2 channels x 8 px -> B tile (bf16 hi/lo, swizzled)
        {
            const int k0 = cp << 1, c0 = (ci << 5) + k0;
            float wA[9], wB[9];
#pragma unroll
            for (int t = 0; t < 9; t++) { wA[t] = s_wd[c0 * 9 + t]; wB[t] = s_wd[(c0 + 1) * 9 + t]; }
            const float bA = __ldg(bd + c0), bB = __ldg(bd + c0 + 1);
            const float* inA = smf + OFF_IN / 4 + (buf * 32 + k0) * IN_STRIDE + pr * 34 + pc0;
            const float* inB = inA + IN_STRIDE;
            float vA[3][10], vB[3][10];
#pragma unroll
            for (int r = 0; r < 3; r++)
#pragma unroll
                for (int m = 0; m < 10; m++) { vA[r][m] = inA[r * 34 + m]; vB[r][m] = inB[r * 34 + m]; }
            const unsigned Bb = su + OFF_B + (buf << 14);
#pragma unroll
            for (int j = 0; j < 8; j++) {
                float aA = bA, aB = bB;
#pragma unroll
                for (int r = 0; r < 3; r++)
#pragma unroll
                    for (int d = 0; d < 3; d++) {
                        aA = fmaf(wA[r * 3 + d], vA[r][j + d], aA);
                        aB = fmaf(wB[r * 3 + d], vB[r][j + d], aB);
                    }
                const float hA = __bfloat162float(__float2bfloat16(aA));
                const float hB = __bfloat162float(__float2bfloat16(aB));
                const unsigned uh = pack_bf2(aB, aA);            // lower = chA (k=2cp), upper = chB
                const unsigned ul = pack_bf2(aB - hB, aA - hA);
                const int p = (pg << 3) + j;                     // B row = pixel
                const unsigned off = (unsigned)((p << 7) + (cp << 2));
                asm volatile("st.shared.b32 [%0], %1;" :: "r"(Bb + swz(off)), "r"(uh) : "memory");
                asm volatile("st.shared.b32 [%0], %1;" :: "r"(Bb + swz(off + 64)), "r"(ul) : "memory");
            }
        }
        __syncthreads();

        // ---- warp MMA: 32(o) x 64(px) per warp, K=64 per chunk ----
        {
            const unsigned Ab = su + OFF_A + (buf << 14);
            const unsigned Bb = su + OFF_B + (buf << 14);
#pragma unroll
            for (int ks = 0; ks < 4; ks++) {
                const int kb = ks << 5;                           // 32 bytes per k-step
                unsigned a[2][4];
#pragma unroll
                for (int ma = 0; ma < 2; ma++)
                    ldm_x4(Ab + swz((unsigned)(((mw << 5) + (ma << 4) + aRow) << 7) + kb + aChunk), a[ma]);
                unsigned bf[4][4];
#pragma unroll
                for (int nb2 = 0; nb2 < 4; nb2++)
                    ldm_x4(Bb + swz((unsigned)(((nw << 6) + (nb2 << 4) + bRow) << 7) + kb + bChunk), bf[nb2]);
#pragma unroll
                for (int ma = 0; ma < 2; ma++)
#pragma unroll
                    for (int nb = 0; nb < 8; nb++)
                        mma16816(acc[ma][nb], a[ma],
                                 bf[nb >> 1][(nb & 1) << 1], bf[nb >> 1][((nb & 1) << 1) + 1]);
            }
        }
    }

    // ---- epilogue: acc regs -> smem stage -> coalesced global stores ----
    __syncthreads();                        // done with all smem tiles
    float* s_ep = smf + OFF_A / 4;          // 128 x 132 floats (overlaps A/B/WD, all dead)
#pragma unroll
    for (int ma = 0; ma < 2; ma++)
#pragma unroll
        for (int nb = 0; nb < 8; nb++) {
            const int o0 = (mw << 5) + (ma << 4) + (lid >> 2);
            const int p0 = (nw << 6) + (nb << 3) + ((lid & 3) << 1);
            *reinterpret_cast<float2*>(&s_ep[o0 * EP_STRIDE + p0]) =
                make_float2(acc[ma][nb][0], acc[ma][nb][1]);
            *reinterpret_cast<float2*>(&s_ep[(o0 + 8) * EP_STRIDE + p0]) =
                make_float2(acc[ma][nb][2], acc[ma][nb][3]);
        }
    __syncthreads();

    const float ws = g_wpscale[MODE];
#pragma unroll
    for (int it = 0; it < 16; it++) {
        const int prr = it >> 2;
        const int o   = (tid >> 3) + ((it & 3) << 5);
        const int pcq = (tid & 7) << 2;
        const float bpv = __ldg(bp + o);
        const float4 d4 = *reinterpret_cast<const float4*>(&s_ep[o * EP_STRIDE + prr * 32 + pcq]);
        float4 v;
        v.x = fmaf(d4.x, ws, bpv); v.y = fmaf(d4.y, ws, bpv);
        v.z = fmaf(d4.z, ws, bpv); v.w = fmaf(d4.w, ws, bpv);
        const int gidx = (((b << 7) + o) << 13) + ((y0 + prr) << 7) + x0 + pcq;
        if (MODE == 0) {
            float4 r4 = make_float4(sigmoidf_(v.x), sigmoidf_(v.y), sigmoidf_(v.z), sigmoidf_(v.w));
            *reinterpret_cast<float4*>(&g_z[gidx]) = r4;
        } else if (MODE == 1) {
            const float4 h4 = *reinterpret_cast<const float4*>(&h[gidx]);
            float4 r4 = make_float4(h4.x * sigmoidf_(v.x), h4.y * sigmoidf_(v.y),
                                    h4.z * sigmoidf_(v.z), h4.w * sigmoidf_(v.w));
            *reinterpret_cast<float4*>(&g_rh[gidx]) = r4;
        } else {
            const float4 h4 = *reinterpret_cast<const float4*>(&h[gidx]);
            const float4 z4 = *reinterpret_cast<const float4*>(&g_z[gidx]);
            float4 r4;
            r4.x = fmaf(z4.x, tanhf(v.x) - h4.x, h4.x);
            r4.y = fmaf(z4.y, tanhf(v.y) - h4.y, h4.y);
            r4.z = fmaf(z4.z, tanhf(v.z) - h4.z, h4.z);
            r4.w = fmaf(z4.w, tanhf(v.w) - h4.w, h4.w);
            *reinterpret_cast<float4*>(&dout[gidx]) = r4;
        }
    }
}

// ---- launch ----
extern "C" void kernel_launch(void* const* d_in, const int* in_sizes, int n_in,
                              void* d_out, int out_size) {
    const float* h   = (const float*)d_in[0];
    const float* x   = (const float*)d_in[1];
    const float* wdz = (const float*)d_in[2];
    const float* bdz = (const float*)d_in[3];
    const float* wpz = (const float*)d_in[4];
    const float* bpz = (const float*)d_in[5];
    const float* wdr = (const float*)d_in[6];
    const float* bdr = (const float*)d_in[7];
    const float* wpr = (const float*)d_in[8];
    const float* bpr = (const float*)d_in[9];
    const float* wdq = (const float*)d_in[10];
    const float* bdq = (const float*)d_in[11];
    const float* wpq = (const float*)d_in[12];
    const float* bpq = (const float*)d_in[13];
    float* out = (float*)d_out;

    cudaFuncSetAttribute(gate_kernel<0>, cudaFuncAttributeMaxDynamicSharedMemorySize, SMEM_BYTES);
    cudaFuncSetAttribute(gate_kernel<1>, cudaFuncAttributeMaxDynamicSharedMemorySize, SMEM_BYTES);
    cudaFuncSetAttribute(gate_kernel<2>, cudaFuncAttributeMaxDynamicSharedMemorySize, SMEM_BYTES);

    quant_prep_kernel<<<6, 256>>>(wdz, wpz, wdr, wpr, wdq, wpq);

    dim3 grid(IMW / 32, IMH / 4, BATCH);   // (4, 16, 8) = 512 blocks
    gate_kernel<0><<<grid, 256, SMEM_BYTES>>>(h, x, bdz, bpz, nullptr);
    gate_kernel<1><<<grid, 256, SMEM_BYTES>>>(h, x, bdr, bpr, nullptr);
    gate_kernel<2><<<grid, 256, SMEM_BYTES>>>(h, x, bdq, bpq, out);
}